// round 2
// baseline (speedup 1.0000x reference)
#include <cuda_runtime.h>
#include <math.h>

// SparseMixerMoeRoutingMethod: top-2 routing over 64 experts with the
// sparse-mixer relative mask.
//
// Layout: 8 lanes per token (4 tokens per warp). Each lane owns 8 contiguous
// experts loaded as 2x float4 (warp consumes 1KiB contiguous -> full sector
// utilization). Reductions are 3-step shfl_xor within the 8-lane group, so
// the shfl cost is amortized over 4 tokens per warp instruction.
//
// Math: sel_i = softmax(masked)[argmax] = 1 / sum_{kept} exp(x - max_i).
// keep <=> (max - x) <= 0.2 * max(|x|, max)  (division-free rewrite of the
// reference mask; -inf entries give inf <= inf -> kept, exp(-inf) = 0,
// matching the reference's NaN->False->kept-at--inf semantics).
//
// Output buffer is a single float32 array: indices cast to float in
// [0, 2n), values in [2n, 4n)  (reference tuple order, common dtype fp32).

#define NUM_EXPERTS 64

__global__ void __launch_bounds__(256)
sparse_mixer_routing_kernel(const float* __restrict__ logits,
                            float* __restrict__ out,
                            int n_tokens) {
    const int warp  = (blockIdx.x * blockDim.x + threadIdx.x) >> 5;
    const int lane  = threadIdx.x & 31;
    const int grp   = lane >> 3;          // 4 token-groups per warp
    const int sub   = lane & 7;           // lane within group
    const int token = warp * 4 + grp;
    const bool valid = (token < n_tokens);
    const int tok_c  = valid ? token : (n_tokens - 1);   // clamp, keep lanes converged

    // Each lane: 8 contiguous experts = 2x float4.
    const float4* row =
        reinterpret_cast<const float4*>(logits + (size_t)tok_c * NUM_EXPERTS);
    const float4 v0 = row[sub * 2];
    const float4 v1 = row[sub * 2 + 1];
    const float x[8] = {v0.x, v0.y, v0.z, v0.w, v1.x, v1.y, v1.z, v1.w};
    const int base = sub * 8;

    int   prev = -1;
    float vals[2];
    int   idxs[2];

    #pragma unroll
    for (int pass = 0; pass < 2; ++pass) {
        // Local max/argmax over this lane's 8 experts, excluding prev.
        // First-occurrence (lowest index) wins ties, matching jnp.argmax.
        float m  = -INFINITY;
        int   mi = NUM_EXPERTS;           // sentinel > any real index
        #pragma unroll
        for (int j = 0; j < 8; ++j) {
            const float a = (base + j == prev) ? -INFINITY : x[j];
            if (a > m || (a == m && base + j < mi)) { m = a; mi = base + j; }
        }
        // Group (8-lane) max/argmax reduction.
        #pragma unroll
        for (int off = 4; off > 0; off >>= 1) {
            const float om  = __shfl_xor_sync(0xffffffffu, m,  off);
            const int   omi = __shfl_xor_sync(0xffffffffu, mi, off);
            if (om > m || (om == m && omi < mi)) { m = om; mi = omi; }
        }

        // Kept-sum of exp(x - m); __expf only on kept entries (~1-3 per row).
        float s = 0.0f;
        #pragma unroll
        for (int j = 0; j < 8; ++j) {
            const float a = (base + j == prev) ? -INFINITY : x[j];
            if (m - a <= 0.2f * fmaxf(fabsf(a), m)) s += __expf(a - m);
        }
        #pragma unroll
        for (int off = 4; off > 0; off >>= 1)
            s += __shfl_xor_sync(0xffffffffu, s, off);

        vals[pass] = 1.0f / s;            // exp(m - m) / sum = 1 / sum
        idxs[pass] = mi;
        prev = mi;
    }

    if (sub == 0 && valid) {
        // Indices as float32 (harness uses one common output dtype).
        reinterpret_cast<float2*>(out)[token] =
            make_float2((float)idxs[0], (float)idxs[1]);
        reinterpret_cast<float2*>(out + 2 * (size_t)n_tokens)[token] =
            make_float2(vals[0], vals[1]);
    }
}

extern "C" void kernel_launch(void* const* d_in, const int* in_sizes, int n_in,
                              void* d_out, int out_size) {
    const float* logits = (const float*)d_in[0];
    const int n_tokens  = in_sizes[0] / NUM_EXPERTS;

    float* out = (float*)d_out;

    const int threads = 256;                       // 8 warps = 32 tokens/block
    const int tokens_per_block = (threads / 32) * 4;
    const int blocks = (n_tokens + tokens_per_block - 1) / tokens_per_block;
    sparse_mixer_routing_kernel<<<blocks, threads>>>(logits, out, n_tokens);
}

// round 4
// speedup vs baseline: 1.4208x; 1.4208x over previous
#include <cuda_runtime.h>
#include <math.h>

// SparseMixerMoeRoutingMethod: top-2 routing over 64 experts, sparse-mixer mask.
//
// Layout: 8 lanes/token, 4 tokens/warp; each lane owns 8 contiguous experts
// (2x float4, warp reads 1KiB contiguous).
//
// Algorithm (per token, exact w.r.t. the reference semantics):
//   - one multiset top-2 scan gives m1 (pass-1 max) and m2 (pass-2 max after
//     masking the argmax position) -- no re-scan, no prev-masking SELs.
//   - indices by equality-match + ballot (lowest index wins, matching
//     jnp.argmax first-occurrence; mi2 excludes the mi1 position).
//   - sparse-mixer keep test: for m > 0 (always true for the max of 64
//     N(0,1) logits; exact general fallback otherwise):
//       keep <=> (m - x) <= 0.2 * max(|x|, m)  <=>  x >= 0.8 * m
//     sel = softmax(masked)[argmax] = 1 / sum_{kept} exp(x - m).
//
// Output: single fp32 buffer, [indices-as-float (2n) | values (2n)].

#define NUM_EXPERTS 64
#define L2E 1.4426950408889634f

__global__ void __launch_bounds__(256)
sparse_mixer_routing_kernel(const float* __restrict__ logits,
                            float* __restrict__ out,
                            int n_tokens) {
    const int warp  = (blockIdx.x * blockDim.x + threadIdx.x) >> 5;
    const int lane  = threadIdx.x & 31;
    const int grp   = lane >> 3;
    const int sub   = lane & 7;
    const int token = warp * 4 + grp;
    const bool valid = (token < n_tokens);
    const int tok_c  = valid ? token : (n_tokens - 1);

    const float4* row =
        reinterpret_cast<const float4*>(logits + (size_t)tok_c * NUM_EXPERTS);
    const float4 p0 = row[sub * 2];
    const float4 p1 = row[sub * 2 + 1];
    const float x[8] = {p0.x, p0.y, p0.z, p0.w, p1.x, p1.y, p1.z, p1.w};
    const int base = sub * 8;

    // ---- multiset top-2 values (local scan, 3 FMNMX/elem) ----
    float m1 = -INFINITY, m2 = -INFINITY;
    #pragma unroll
    for (int j = 0; j < 8; ++j) {
        m2 = fmaxf(m2, fminf(m1, x[j]));
        m1 = fmaxf(m1, x[j]);
    }
    // reduce top-2 across the 8-lane group
    #pragma unroll
    for (int off = 4; off > 0; off >>= 1) {
        const float om1 = __shfl_xor_sync(0xffffffffu, m1, off);
        const float om2 = __shfl_xor_sync(0xffffffffu, m2, off);
        m2 = fmaxf(m2, fminf(m1, om1));
        m2 = fmaxf(m2, om2);
        m1 = fmaxf(m1, om1);
    }

    // ---- mi1: lowest index with x == m1 (matches jnp.argmax ties) ----
    int mj1 = 8;
    #pragma unroll
    for (int j = 7; j >= 0; --j)
        if (x[j] == m1) mj1 = j;
    const unsigned bal1 = __ballot_sync(0xffffffffu, mj1 < 8);
    const unsigned g1   = (bal1 >> (grp * 8)) & 0xffu;
    const int src1      = (grp << 3) + (__ffs(g1) - 1);
    const int mi1       = __shfl_sync(0xffffffffu, base + mj1, src1);

    // ---- mi2: lowest index with x == m2, excluding position mi1 ----
    int mj2 = 8;
    #pragma unroll
    for (int j = 7; j >= 0; --j)
        if (x[j] == m2 && (base + j) != mi1) mj2 = j;
    const unsigned bal2 = __ballot_sync(0xffffffffu, mj2 < 8);
    const unsigned g2   = (bal2 >> (grp * 8)) & 0xffu;
    const int src2      = (grp << 3) + (__ffs(g2) - 1);
    const int mi2       = __shfl_sync(0xffffffffu, base + mj2, src2);

    // ---- kept-sums of exp(x - m) for both passes ----
    float s1 = 0.0f, s2 = 0.0f;
    if (m2 > 0.0f) {
        // Fast path (always taken for N(0,1) data): keep <=> x >= 0.8*m.
        const float thr1 = 0.8f * m1, c1 = -m1 * L2E;
        const float thr2 = 0.8f * m2, c2 = -m2 * L2E;
        #pragma unroll
        for (int j = 0; j < 8; ++j) {
            if (x[j] >= thr1)
                s1 += exp2f(fmaf(x[j], L2E, c1));
            if (x[j] >= thr2 && (base + j) != mi1)
                s2 += exp2f(fmaf(x[j], L2E, c2));
        }
    } else {
        // Exact general guard: keep <=> 0.2*max(|x|,m) + (x - m) >= 0.
        #pragma unroll
        for (int j = 0; j < 8; ++j) {
            const float e1 = x[j] - m1;
            if (fmaf(0.2f, fmaxf(fabsf(x[j]), m1), e1) >= 0.0f)
                s1 += exp2f(e1 * L2E);
            const float e2 = x[j] - m2;
            if (fmaf(0.2f, fmaxf(fabsf(x[j]), m2), e2) >= 0.0f &&
                (base + j) != mi1)
                s2 += exp2f(e2 * L2E);
        }
    }
    // group sum reductions
    #pragma unroll
    for (int off = 4; off > 0; off >>= 1) {
        s1 += __shfl_xor_sync(0xffffffffu, s1, off);
        s2 += __shfl_xor_sync(0xffffffffu, s2, off);
    }
    const float sel1 = __fdividef(1.0f, s1);   // exp(m-m)/sum
    const float sel2 = __fdividef(1.0f, s2);

    if (sub == 0 && valid) {
        reinterpret_cast<float2*>(out)[token] =
            make_float2((float)mi1, (float)mi2);
        reinterpret_cast<float2*>(out + 2 * (size_t)n_tokens)[token] =
            make_float2(sel1, sel2);
    }
}

extern "C" void kernel_launch(void* const* d_in, const int* in_sizes, int n_in,
                              void* d_out, int out_size) {
    const float* logits = (const float*)d_in[0];
    const int n_tokens  = in_sizes[0] / NUM_EXPERTS;

    float* out = (float*)d_out;

    const int threads = 256;                       // 8 warps = 32 tokens/block
    const int tokens_per_block = (threads / 32) * 4;
    const int blocks = (n_tokens + tokens_per_block - 1) / tokens_per_block;
    sparse_mixer_routing_kernel<<<blocks, threads>>>(logits, out, n_tokens);
}

// round 5
// speedup vs baseline: 1.8636x; 1.3117x over previous
#include <cuda_runtime.h>
#include <math.h>

// SparseMixerMoeRoutingMethod: top-2 routing over 64 experts, sparse-mixer mask.
//
// Layout: 8 lanes/token, 4 tokens/warp; each lane owns 8 contiguous experts
// (2x float4, warp reads 1KiB contiguous -> fully coalesced).
//
// Per token (exact w.r.t. reference semantics):
//   - one multiset top-2 value scan + 3-step group reduction -> m1, m2
//     (m2 == pass-2 max after masking the argmax position).
//   - keep test in universal threshold form:
//       keep <=> (m - x) <= 0.2*max(|x|, m) <=> x >= m*(m>0 ? 0.8 : 1.25)
//   - unnormalized exps e_j = ex2(x_j*log2e) computed ONCE per element
//     (single MUFU via inline PTX; exp2f w/o fast-math is a slow routine):
//       s1 = sum_{x>=thr1} e,  s2 = sum_{x>=thr2} e - e_{m1}
//       sel_i = ex2(m_i*log2e) / s_i
//   - indices: lowest position with x==m_i via in-loop match + ballot
//     (jnp.argmax first-occurrence); rare m1==m2 tie handled by a
//     warp-uniform fallback rescan excluding mi1.
//
// Output: single fp32 buffer, [indices-as-float (2n) | values (2n)].

#define NUM_EXPERTS 64
#define L2E 1.4426950408889634f

__device__ __forceinline__ float ex2(float t) {
    float r;
    asm("ex2.approx.ftz.f32 %0, %1;" : "=f"(r) : "f"(t));
    return r;   // ex2(-inf) = 0
}

__global__ void __launch_bounds__(256)
sparse_mixer_routing_kernel(const float* __restrict__ logits,
                            float* __restrict__ out,
                            int n_tokens) {
    const int warp  = (blockIdx.x * blockDim.x + threadIdx.x) >> 5;
    const int lane  = threadIdx.x & 31;
    const int grp   = lane >> 3;
    const int sub   = lane & 7;
    const int token = warp * 4 + grp;
    const bool valid = (token < n_tokens);
    const int tok_c  = valid ? token : (n_tokens - 1);

    const float4* row =
        reinterpret_cast<const float4*>(logits + (size_t)tok_c * NUM_EXPERTS);
    const float4 p0 = row[sub * 2];
    const float4 p1 = row[sub * 2 + 1];
    const float x[8] = {p0.x, p0.y, p0.z, p0.w, p1.x, p1.y, p1.z, p1.w};
    const int base = sub * 8;

    // ---- multiset top-2 values: local scan (3 FMNMX/elem) ----
    float m1 = x[0], m2 = -INFINITY;
    #pragma unroll
    for (int j = 1; j < 8; ++j) {
        m2 = fmaxf(m2, fminf(m1, x[j]));
        m1 = fmaxf(m1, x[j]);
    }
    // ---- 8-lane group top-2 reduction ----
    #pragma unroll
    for (int off = 4; off > 0; off >>= 1) {
        const float om1 = __shfl_xor_sync(0xffffffffu, m1, off);
        const float om2 = __shfl_xor_sync(0xffffffffu, m2, off);
        m2 = fmaxf(fmaxf(m2, om2), fminf(m1, om1));
        m1 = fmaxf(m1, om1);
    }

    // ---- universal keep thresholds (exact for any sign of m) ----
    const float thr1 = m1 * (m1 > 0.0f ? 0.8f : 1.25f);
    const float thr2 = m2 * (m2 > 0.0f ? 0.8f : 1.25f);

    // ---- fused match + exp loop ----
    int   mj1 = 8, mj2 = 8;
    float s1 = 0.0f, s2 = 0.0f;
    #pragma unroll
    for (int j = 7; j >= 0; --j) {          // descending: lowest j wins match
        const float xj = x[j];
        if (xj == m1) mj1 = j;
        if (xj == m2) mj2 = j;
        const float t = (xj >= thr2) ? xj : -INFINITY;  // thr2 <= thr1
        const float e = ex2(t * L2E);
        s2 += e;
        if (xj >= thr1) s1 += e;
    }

    // ---- index recovery via ballot (first occurrence across the group) ----
    const unsigned b1 = __ballot_sync(0xffffffffu, mj1 < 8);
    const unsigned b2 = __ballot_sync(0xffffffffu, mj2 < 8);
    const int lanebase = grp << 3;
    const int src1 = lanebase + (__ffs((b1 >> lanebase) & 0xffu) - 1);
    const int src2 = lanebase + (__ffs((b2 >> lanebase) & 0xffu) - 1);
    const int mi1  = __shfl_sync(0xffffffffu, base + mj1, src1);
    int       mi2  = __shfl_sync(0xffffffffu, base + mj2, src2);

    // ---- rare exact-tie fallback (m1 == m2): exclude position mi1 ----
    if (__ballot_sync(0xffffffffu, mi2 == mi1)) {
        int mj = 8;
        #pragma unroll
        for (int j = 7; j >= 0; --j)
            if (x[j] == m2 && (base + j) != mi1) mj = j;
        const unsigned bb = __ballot_sync(0xffffffffu, mj < 8);
        const int src = lanebase + (__ffs((bb >> lanebase) & 0xffu) - 1);
        mi2 = __shfl_sync(0xffffffffu, base + mj, src);
    }

    // ---- group sum reductions ----
    #pragma unroll
    for (int off = 4; off > 0; off >>= 1) {
        s1 += __shfl_xor_sync(0xffffffffu, s1, off);
        s2 += __shfl_xor_sync(0xffffffffu, s2, off);
    }

    const float em1 = ex2(m1 * L2E);
    const float em2 = ex2(m2 * L2E);
    const float sel1 = __fdividef(em1, s1);
    const float sel2 = __fdividef(em2, s2 - em1);  // mi1 always in kept2 set

    if (sub == 0 && valid) {
        reinterpret_cast<float2*>(out)[token] =
            make_float2((float)mi1, (float)mi2);
        reinterpret_cast<float2*>(out + 2 * (size_t)n_tokens)[token] =
            make_float2(sel1, sel2);
    }
}

extern "C" void kernel_launch(void* const* d_in, const int* in_sizes, int n_in,
                              void* d_out, int out_size) {
    const float* logits = (const float*)d_in[0];
    const int n_tokens  = in_sizes[0] / NUM_EXPERTS;

    float* out = (float*)d_out;

    const int threads = 256;                       // 8 warps = 32 tokens/block
    const int tokens_per_block = (threads / 32) * 4;
    const int blocks = (n_tokens + tokens_per_block - 1) / tokens_per_block;
    sparse_mixer_routing_kernel<<<blocks, threads>>>(logits, out, n_tokens);
}

// round 6
// speedup vs baseline: 2.3525x; 1.2623x over previous
#include <cuda_runtime.h>
#include <math.h>

// SparseMixerMoeRoutingMethod: top-2 routing over 64 experts, sparse-mixer mask.
//
// Layout: 4 lanes/token (16 experts/lane via 4x LDG.128), 8 tokens/warp.
// Two-phase sparse algorithm:
//   A) dense multiset top-2 scan + 2-step group reduce -> m1, m2.
//      keep <=> (m-x) <= 0.2*max(|x|,m) <=> x >= m*(m>0 ? 0.8 : 1.25) (exact).
//   B) dense 16-bit candidate mask of x >= thr2 (contains every kept entry of
//      BOTH passes, incl. the m1/m2 positions).
//   C) sparse gather over set bits (~0.6 avg/lane): reload element (L1 hit),
//      one ex2 serves both passes, equality matches give indices.
//      s1 = sum_{x>=thr1} e ;  s2 = sum_{x>=thr2} e - e_{m1}
//      sel_i = ex2(m_i*log2e) / s_i   (unnormalized exps, exact ratio).
//   Indices: lowest position with x==m_i (jnp.argmax first-occurrence);
//   m1==m2 tie handled via sorted-pair (two-smallest) reduction.
//
// Output: single fp32 buffer, [indices-as-float (2n) | values (2n)].

#define NUM_EXPERTS 64
#define L2E 1.4426950408889634f
#define SENT 127

__device__ __forceinline__ float ex2(float t) {
    float r;
    asm("ex2.approx.ftz.f32 %0, %1;" : "=f"(r) : "f"(t));
    return r;
}

__global__ void __launch_bounds__(256)
sparse_mixer_routing_kernel(const float* __restrict__ logits,
                            float* __restrict__ out,
                            int n_tokens) {
    const int warp  = (blockIdx.x * blockDim.x + threadIdx.x) >> 5;
    const int lane  = threadIdx.x & 31;
    const int grp   = lane >> 2;          // 8 token-groups of 4 lanes
    const int sub   = lane & 3;
    const int token = warp * 8 + grp;
    const bool valid = (token < n_tokens);
    const int tok_c  = valid ? token : (n_tokens - 1);

    // Each lane owns 16 contiguous experts (4x float4; warp reads 2KiB contig).
    const float* seg = logits + (size_t)tok_c * NUM_EXPERTS + sub * 16;
    const float4* s4 = reinterpret_cast<const float4*>(seg);
    float x[16];
    {
        const float4 a = s4[0], b = s4[1], c = s4[2], d = s4[3];
        x[0]=a.x; x[1]=a.y; x[2]=a.z;  x[3]=a.w;
        x[4]=b.x; x[5]=b.y; x[6]=b.z;  x[7]=b.w;
        x[8]=c.x; x[9]=c.y; x[10]=c.z; x[11]=c.w;
        x[12]=d.x;x[13]=d.y;x[14]=d.z; x[15]=d.w;
    }

    // ---- Phase A: multiset top-2 (local scan, 3 FMNMX/elem) ----
    float m1 = x[0], m2 = -INFINITY;
    #pragma unroll
    for (int j = 1; j < 16; ++j) {
        m2 = fmaxf(m2, fminf(m1, x[j]));
        m1 = fmaxf(m1, x[j]);
    }
    // 4-lane group top-2 reduction (xor offsets 1,2 stay within the group)
    #pragma unroll
    for (int off = 2; off > 0; off >>= 1) {
        const float om1 = __shfl_xor_sync(0xffffffffu, m1, off);
        const float om2 = __shfl_xor_sync(0xffffffffu, m2, off);
        m2 = fmaxf(fmaxf(m2, om2), fminf(m1, om1));
        m1 = fmaxf(m1, om1);
    }

    // Universal keep thresholds (exact for any sign of m).
    const float thr1 = m1 * (m1 > 0.0f ? 0.8f : 1.25f);
    const float thr2 = m2 * (m2 > 0.0f ? 0.8f : 1.25f);

    // ---- Phase B: candidate mask (x >= thr2; thr2 <= thr1) ----
    unsigned mask = 0;
    #pragma unroll
    for (int j = 0; j < 16; ++j)
        if (x[j] >= thr2) mask |= (1u << j);

    // ---- Phase C: sparse gather over candidates ----
    const int base = sub * 16;
    float s1 = 0.0f, s2 = 0.0f;
    int mj1 = SENT, mj2 = SENT, mj2b = SENT;   // mj2 <= mj2b (two lowest m2 hits)
    while (mask) {
        const int j = __ffs(mask) - 1;
        mask &= mask - 1;                       // ascending j order
        const float v = __ldg(seg + j);         // L1 hit: row just loaded
        const float e = ex2(v * L2E);
        s2 += e;
        if (v >= thr1) s1 += e;
        const int gj = base + j;
        if (v == m1) mj1 = min(mj1, gj);        // first hit is lowest (asc.)
        if (v == m2) {
            if (mj2 == SENT) mj2 = gj;
            else if (mj2b == SENT) mj2b = gj;
        }
    }

    // ---- group reductions (converged here) ----
    #pragma unroll
    for (int off = 2; off > 0; off >>= 1) {
        s1  += __shfl_xor_sync(0xffffffffu, s1, off);
        s2  += __shfl_xor_sync(0xffffffffu, s2, off);
        mj1  = min(mj1, __shfl_xor_sync(0xffffffffu, mj1, off));
        // two-smallest (sorted pair) reduce for m2 matches
        const int oa = __shfl_xor_sync(0xffffffffu, mj2,  off);
        const int ob = __shfl_xor_sync(0xffffffffu, mj2b, off);
        const int lo = min(mj2, oa);
        mj2b = min(max(mj2, oa), min(mj2b, ob));
        mj2  = lo;
    }

    const int mi1 = mj1;
    // m1 != m2: m2-matches are disjoint from position mi1 -> mj2.
    // m1 == m2 (exact tie): mj2 == mi1, masked in pass 2 -> second-lowest.
    const int mi2 = (mj2 == mi1) ? mj2b : mj2;

    const float em1 = ex2(m1 * L2E);
    const float em2 = ex2(m2 * L2E);
    const float sel1 = __fdividef(em1, s1);
    const float sel2 = __fdividef(em2, s2 - em1);  // mi1 always in kept2 superset

    if (sub == 0 && valid) {
        reinterpret_cast<float2*>(out)[token] =
            make_float2((float)mi1, (float)mi2);
        reinterpret_cast<float2*>(out + 2 * (size_t)n_tokens)[token] =
            make_float2(sel1, sel2);
    }
}

extern "C" void kernel_launch(void* const* d_in, const int* in_sizes, int n_in,
                              void* d_out, int out_size) {
    const float* logits = (const float*)d_in[0];
    const int n_tokens  = in_sizes[0] / NUM_EXPERTS;

    float* out = (float*)d_out;

    const int threads = 256;                 // 8 warps = 64 tokens/block
    const int tokens_per_block = (threads / 32) * 8;
    const int blocks = (n_tokens + tokens_per_block - 1) / tokens_per_block;
    sparse_mixer_routing_kernel<<<blocks, threads>>>(logits, out, n_tokens);
}

// round 7
// speedup vs baseline: 2.4118x; 1.0252x over previous
#include <cuda_runtime.h>
#include <math.h>

// SparseMixerMoeRoutingMethod: top-2 routing over 64 experts, sparse-mixer mask.
//
// Layout: 4 lanes/token (16 experts/lane via 4x LDG.128), 8 tokens/warp.
//   A) dense multiset top-2 scan (3 FMNMX/elem) + 2-step group reduce -> m1,m2
//      keep <=> (m-x) <= 0.2*max(|x|,m) <=> x >= m*(m>0 ? 0.8 : 1.25) (exact).
//   B) 16-bit candidate mask of x >= thr2 (superset of both passes' kept sets;
//      contains the m1 and m2 positions by construction).
//   C) sparse gather over set bits (~0.6 avg/lane): reload elem (L1 hit),
//      m1-relative exp e = ex2((x-m1)*log2e) serves both passes:
//        s1 = sum_{x>=thr1} e            -> sel1 = 1/s1
//        s2 = sum_{x>=thr2} e            -> sel2 = ex2((m2-m1)*log2e)/(s2 - 1)
//      (the m1 term contributes exactly ~1 to s2; subtracting 1 removes it,
//       which stays correct under exact m1==m2 ties.)
//   Indices: lowest position with x==m_i (jnp.argmax first-occurrence) via
//   local-j tracking in the gather + ballot/ffs/shfl recovery; rare exact
//   m1==m2 tie resolved by a ballot-guarded fallback rescan.
//
// Output: single fp32 buffer, [indices-as-float (2n) | values (2n)].

#define NUM_EXPERTS 64
#define L2E 1.4426950408889634f

__device__ __forceinline__ float ex2(float t) {
    float r;
    asm("ex2.approx.ftz.f32 %0, %1;" : "=f"(r) : "f"(t));
    return r;
}
__device__ __forceinline__ float rcp(float t) {
    float r;
    asm("rcp.approx.ftz.f32 %0, %1;" : "=f"(r) : "f"(t));
    return r;
}

__global__ void __launch_bounds__(256)
sparse_mixer_routing_kernel(const float* __restrict__ logits,
                            float* __restrict__ out,
                            int n_tokens) {
    const int warp  = (blockIdx.x * blockDim.x + threadIdx.x) >> 5;
    const int lane  = threadIdx.x & 31;
    const int grp   = lane >> 2;          // 8 token-groups of 4 lanes
    const int sub   = lane & 3;
    const int token = warp * 8 + grp;
    const bool valid = (token < n_tokens);
    const int tok_c  = valid ? token : (n_tokens - 1);

    const float* seg = logits + (size_t)tok_c * NUM_EXPERTS + sub * 16;
    const float4* s4 = reinterpret_cast<const float4*>(seg);
    float x[16];
    {
        const float4 a = s4[0], b = s4[1], c = s4[2], d = s4[3];
        x[0]=a.x; x[1]=a.y; x[2]=a.z;  x[3]=a.w;
        x[4]=b.x; x[5]=b.y; x[6]=b.z;  x[7]=b.w;
        x[8]=c.x; x[9]=c.y; x[10]=c.z; x[11]=c.w;
        x[12]=d.x;x[13]=d.y;x[14]=d.z; x[15]=d.w;
    }

    // ---- A: multiset top-2 local scan ----
    float m1 = x[0], m2 = -INFINITY;
    #pragma unroll
    for (int j = 1; j < 16; ++j) {
        m2 = fmaxf(m2, fminf(m1, x[j]));
        m1 = fmaxf(m1, x[j]);
    }
    // 4-lane group top-2 reduction (xor 2,1 stay in-group)
    #pragma unroll
    for (int off = 2; off > 0; off >>= 1) {
        const float om1 = __shfl_xor_sync(0xffffffffu, m1, off);
        const float om2 = __shfl_xor_sync(0xffffffffu, m2, off);
        m2 = fmaxf(fmaxf(m2, om2), fminf(m1, om1));
        m1 = fmaxf(m1, om1);
    }

    const float thr1 = m1 * (m1 > 0.0f ? 0.8f : 1.25f);
    const float thr2 = m2 * (m2 > 0.0f ? 0.8f : 1.25f);
    const float c1   = -m1 * L2E;

    // ---- B: candidate mask (x >= thr2; thr2 <= thr1) ----
    unsigned mask = 0;
    #pragma unroll
    for (int j = 0; j < 16; ++j)
        if (x[j] >= thr2) mask |= (1u << j);

    // ---- C: sparse gather ----
    float s1 = 0.0f, s2 = 0.0f;
    int mj1 = 31, mj2 = 31;                 // local j of first m1/m2 match
    while (mask) {
        const int j = __ffs(mask) - 1;      // ascending j
        mask &= mask - 1;
        const float v = __ldg(seg + j);     // L1 hit (row just loaded)
        const float e = ex2(fmaf(v, L2E, c1));
        s2 += e;
        if (v >= thr1) s1 += e;
        if (v == m1) mj1 = min(mj1, j);
        if (v == m2) mj2 = min(mj2, j);
    }

    // ---- index recovery: ballot + ffs + shfl (first occurrence) ----
    const unsigned b1 = __ballot_sync(0xffffffffu, mj1 < 31);
    const unsigned b2 = __ballot_sync(0xffffffffu, mj2 < 31);
    const int gsh = grp << 2;
    const int src1 = gsh + (__ffs((b1 >> gsh) & 0xFu) - 1);
    const int src2 = gsh + (__ffs((b2 >> gsh) & 0xFu) - 1);
    const int mi1  = ((src1 & 3) << 4) | __shfl_sync(0xffffffffu, mj1, src1);
    int       mi2  = ((src2 & 3) << 4) | __shfl_sync(0xffffffffu, mj2, src2);

    // ---- rare exact-tie fallback: m1 == m2 -> second occurrence ----
    if (__ballot_sync(0xffffffffu, m1 == m2)) {
        int lo = 127, hi = 127;             // global idx of two lowest matches
        #pragma unroll
        for (int j = 15; j >= 0; --j) {
            if (x[j] == m2) { hi = lo; lo = (sub << 4) | j; }
        }
        #pragma unroll
        for (int off = 2; off > 0; off >>= 1) {
            const int oa = __shfl_xor_sync(0xffffffffu, lo, off);
            const int ob = __shfl_xor_sync(0xffffffffu, hi, off);
            const int nl = min(lo, oa);
            hi = min(max(lo, oa), min(hi, ob));
            lo = nl;
        }
        if (m1 == m2) mi2 = hi;             // lo == mi1 (masked in pass 2)
    }

    // ---- group sum reductions ----
    #pragma unroll
    for (int off = 2; off > 0; off >>= 1) {
        s1 += __shfl_xor_sync(0xffffffffu, s1, off);
        s2 += __shfl_xor_sync(0xffffffffu, s2, off);
    }

    const float sel1 = rcp(s1);
    const float sel2 = ex2(fmaf(m2, L2E, c1)) * rcp(s2 - 1.0f);

    if (sub == 0 && valid) {
        reinterpret_cast<float2*>(out)[token] =
            make_float2((float)mi1, (float)mi2);
        reinterpret_cast<float2*>(out + 2 * (size_t)n_tokens)[token] =
            make_float2(sel1, sel2);
    }
}

extern "C" void kernel_launch(void* const* d_in, const int* in_sizes, int n_in,
                              void* d_out, int out_size) {
    const float* logits = (const float*)d_in[0];
    const int n_tokens  = in_sizes[0] / NUM_EXPERTS;

    float* out = (float*)d_out;

    const int threads = 256;                 // 8 warps = 64 tokens/block
    const int tokens_per_block = (threads / 32) * 8;
    const int blocks = (n_tokens + tokens_per_block - 1) / tokens_per_block;
    sparse_mixer_routing_kernel<<<blocks, threads>>>(logits, out, n_tokens);
}

// round 8
// speedup vs baseline: 2.4957x; 1.0348x over previous
#include <cuda_runtime.h>
#include <math.h>

// SparseMixerMoeRoutingMethod: top-2 routing over 64 experts, sparse-mixer mask.
//
// Layout: 4 lanes/token (16 experts/lane via 4x LDG.128), 8 tokens/warp.
//   A) dense multiset top-2 scan (3 FMNMX/elem) + 2-step group reduce -> m1,m2
//      keep <=> (m-x) <= 0.2*max(|x|,m) <=> x >= m*(m>0 ? 0.8 : 1.25) (exact).
//   B) 16-bit candidate mask of x >= thr2 (superset of both passes' kept sets).
//      The row registers DIE here (tie-fallback reloads via __ldg) -> low regs,
//      high occupancy.
//   C) sparse gather over set bits (~0.6 avg/lane): reload elem (L1 hit),
//      m1-relative exp e = ex2((x-m1)*log2e) serves both passes:
//        s1 = sum_{x>=thr1} e            -> sel1 = 1/s1
//        s2 = sum_{x>=thr2} e            -> sel2 = ex2((m2-m1)*log2e)/(s2 - 1)
//      Index matches tracked as global-index mins in the same loop.
//   D) one fused 2-step shfl reduction for {s1, s2, mi1, mi2}.
//   Rare exact m1==m2 tie: ballot-guarded fallback rescan (__ldg, L1-hot)
//   finds the lowest m2-position excluding mi1 (reference masks the argmax).
//
// Output: single fp32 buffer, [indices-as-float (2n) | values (2n)].

#define NUM_EXPERTS 64
#define L2E 1.4426950408889634f

__device__ __forceinline__ float ex2(float t) {
    float r;
    asm("ex2.approx.ftz.f32 %0, %1;" : "=f"(r) : "f"(t));
    return r;
}
__device__ __forceinline__ float rcp(float t) {
    float r;
    asm("rcp.approx.ftz.f32 %0, %1;" : "=f"(r) : "f"(t));
    return r;
}

__global__ void __launch_bounds__(256, 8)
sparse_mixer_routing_kernel(const float* __restrict__ logits,
                            float* __restrict__ out,
                            int n_tokens) {
    const int warp  = (blockIdx.x * blockDim.x + threadIdx.x) >> 5;
    const int lane  = threadIdx.x & 31;
    const int grp   = lane >> 2;          // 8 token-groups of 4 lanes
    const int sub   = lane & 3;
    const int token = warp * 8 + grp;
    const bool valid = (token < n_tokens);
    const int tok_c  = valid ? token : (n_tokens - 1);

    const float* seg = logits + (size_t)tok_c * NUM_EXPERTS + sub * 16;
    const int base = sub * 16;

    float m1, m2;
    unsigned mask = 0;
    {
        const float4* s4 = reinterpret_cast<const float4*>(seg);
        float x[16];
        {
            const float4 a = s4[0], b = s4[1], c = s4[2], d = s4[3];
            x[0]=a.x; x[1]=a.y; x[2]=a.z;  x[3]=a.w;
            x[4]=b.x; x[5]=b.y; x[6]=b.z;  x[7]=b.w;
            x[8]=c.x; x[9]=c.y; x[10]=c.z; x[11]=c.w;
            x[12]=d.x;x[13]=d.y;x[14]=d.z; x[15]=d.w;
        }

        // ---- A: multiset top-2 local scan ----
        m1 = x[0]; m2 = -INFINITY;
        #pragma unroll
        for (int j = 1; j < 16; ++j) {
            m2 = fmaxf(m2, fminf(m1, x[j]));
            m1 = fmaxf(m1, x[j]);
        }
        // 4-lane group top-2 reduction (xor 2,1 stay in-group)
        #pragma unroll
        for (int off = 2; off > 0; off >>= 1) {
            const float om1 = __shfl_xor_sync(0xffffffffu, m1, off);
            const float om2 = __shfl_xor_sync(0xffffffffu, m2, off);
            m2 = fmaxf(fmaxf(m2, om2), fminf(m1, om1));
            m1 = fmaxf(m1, om1);
        }

        // ---- B: candidate mask (x >= thr2; thr2 <= thr1) ----
        const float t2 = m2 * (m2 > 0.0f ? 0.8f : 1.25f);
        #pragma unroll
        for (int j = 0; j < 16; ++j)
            if (x[j] >= t2) mask |= (1u << j);
        // x[] is dead from here on (fallback reloads via __ldg).
    }

    const float thr1 = m1 * (m1 > 0.0f ? 0.8f : 1.25f);
    const float thr2 = m2 * (m2 > 0.0f ? 0.8f : 1.25f);
    const float c1   = -m1 * L2E;

    // ---- C: sparse gather ----
    float s1 = 0.0f, s2 = 0.0f;
    int mi1 = 127, mi2 = 127;               // global-index mins of matches
    while (mask) {
        const int j = __ffs(mask) - 1;
        mask &= mask - 1;
        const float v = __ldg(seg + j);      // L1 hit (row just loaded)
        const float e = ex2(fmaf(v, L2E, c1));
        s2 += e;
        if (v >= thr1) s1 += e;
        const int gj = base + j;
        if (v == m1) mi1 = min(mi1, gj);
        if (v == m2) mi2 = min(mi2, gj);
    }

    // ---- D: fused group reduction: sums + index mins (2 steps) ----
    #pragma unroll
    for (int off = 2; off > 0; off >>= 1) {
        s1 += __shfl_xor_sync(0xffffffffu, s1, off);
        s2 += __shfl_xor_sync(0xffffffffu, s2, off);
        mi1 = min(mi1, __shfl_xor_sync(0xffffffffu, mi1, off));
        mi2 = min(mi2, __shfl_xor_sync(0xffffffffu, mi2, off));
    }

    // ---- rare exact-tie fallback: m1 == m2 -> lowest m2-pos excluding mi1 ----
    if (__ballot_sync(0xffffffffu, m1 == m2)) {
        int sec = 127;
        #pragma unroll
        for (int j = 0; j < 16; ++j) {
            const float v = __ldg(seg + j);  // L1-hot
            const int gj = base + j;
            if (v == m2 && gj != mi1) sec = min(sec, gj);
        }
        #pragma unroll
        for (int off = 2; off > 0; off >>= 1)
            sec = min(sec, __shfl_xor_sync(0xffffffffu, sec, off));
        if (m1 == m2) mi2 = sec;
    }

    const float sel1 = rcp(s1);
    const float sel2 = ex2(fmaf(m2, L2E, c1)) * rcp(s2 - 1.0f);

    if (sub == 0 && valid) {
        reinterpret_cast<float2*>(out)[token] =
            make_float2((float)mi1, (float)mi2);
        reinterpret_cast<float2*>(out + 2 * (size_t)n_tokens)[token] =
            make_float2(sel1, sel2);
    }
}

extern "C" void kernel_launch(void* const* d_in, const int* in_sizes, int n_in,
                              void* d_out, int out_size) {
    const float* logits = (const float*)d_in[0];
    const int n_tokens  = in_sizes[0] / NUM_EXPERTS;

    float* out = (float*)d_out;

    const int threads = 256;                 // 8 warps = 64 tokens/block
    const int tokens_per_block = (threads / 32) * 8;
    const int blocks = (n_tokens + tokens_per_block - 1) / tokens_per_block;
    sparse_mixer_routing_kernel<<<blocks, threads>>>(logits, out, n_tokens);
}

// round 9
// speedup vs baseline: 2.5175x; 1.0088x over previous
#include <cuda_runtime.h>
#include <math.h>

// SparseMixerMoeRoutingMethod: top-2 routing over 64 experts, sparse-mixer mask.
//
// Layout: 4 lanes/token, 8 tokens/warp, CHUNK-INTERLEAVED ownership:
//   lane sub owns float4 chunks {k*4+sub : k=0..3} of the row, so each
//   LDG.128 warp-instruction covers a contiguous 64B band of 8 consecutive
//   rows -> 8 L1 lines/instr (32 wavefronts/warp, half of the blocked map).
//   Element j (=4k+r) of lane sub corresponds to expert gj = 16k + 4*sub + r.
//
//   A) dense multiset top-2 scan (3 FMNMX/elem) + 2-step group reduce -> m1,m2
//      keep <=> (m-x) <= 0.2*max(|x|,m) <=> x >= m*(m>0 ? 0.8 : 1.25) (exact).
//   B) 16-bit candidate mask of x >= thr2 (superset of both kept sets);
//      row registers die here.
//   C) sparse gather over set bits (~0.6 avg/lane): reload elem (L1 hit),
//      m1-relative exp e = ex2((x-m1)*log2e):
//        s1 = sum_{x>=thr1} e            -> sel1 = 1/s1
//        s2 = sum_{x>=thr2} e            -> sel2 = ex2((m2-m1)*log2e)/(s2 - 1)
//      index matches tracked as global-index mins in the same loop.
//   D) fused 2-step shfl reduction of {s1, s2, mi1, mi2}.
//   Rare exact m1==m2 tie: ballot-guarded rescan (__ldg, L1-hot) for the
//   lowest m2 position excluding mi1.
//
// Output: single fp32 buffer, [indices-as-float (2n) | values (2n)].

#define NUM_EXPERTS 64
#define L2E 1.4426950408889634f

__device__ __forceinline__ float ex2(float t) {
    float r;
    asm("ex2.approx.ftz.f32 %0, %1;" : "=f"(r) : "f"(t));
    return r;
}
__device__ __forceinline__ float rcp(float t) {
    float r;
    asm("rcp.approx.ftz.f32 %0, %1;" : "=f"(r) : "f"(t));
    return r;
}

__global__ void __launch_bounds__(128, 16)
sparse_mixer_routing_kernel(const float* __restrict__ logits,
                            float* __restrict__ out,
                            int n_tokens) {
    const int warp  = (blockIdx.x * blockDim.x + threadIdx.x) >> 5;
    const int lane  = threadIdx.x & 31;
    const int grp   = lane >> 2;          // 8 token-groups of 4 lanes
    const int sub   = lane & 3;
    const int token = warp * 8 + grp;
    const bool valid = (token < n_tokens);
    const int tok_c  = valid ? token : (n_tokens - 1);

    const float* rowp = logits + (size_t)tok_c * NUM_EXPERTS;
    const int lane_off = sub << 2;        // expert offset of this lane's chunks

    float m1, m2;
    unsigned mask = 0;
    {
        const float4* r4 = reinterpret_cast<const float4*>(rowp);
        float x[16];
        #pragma unroll
        for (int k = 0; k < 4; ++k) {
            const float4 v = r4[k * 4 + sub];   // contiguous 64B band per instr
            x[k*4+0] = v.x; x[k*4+1] = v.y; x[k*4+2] = v.z; x[k*4+3] = v.w;
        }

        // ---- A: multiset top-2 local scan ----
        m1 = x[0]; m2 = -INFINITY;
        #pragma unroll
        for (int j = 1; j < 16; ++j) {
            m2 = fmaxf(m2, fminf(m1, x[j]));
            m1 = fmaxf(m1, x[j]);
        }
        // 4-lane group top-2 reduction (xor 2,1 stay in-group)
        #pragma unroll
        for (int off = 2; off > 0; off >>= 1) {
            const float om1 = __shfl_xor_sync(0xffffffffu, m1, off);
            const float om2 = __shfl_xor_sync(0xffffffffu, m2, off);
            m2 = fmaxf(fmaxf(m2, om2), fminf(m1, om1));
            m1 = fmaxf(m1, om1);
        }

        // ---- B: candidate mask (x >= thr2) ----
        const float t2 = m2 * (m2 > 0.0f ? 0.8f : 1.25f);
        #pragma unroll
        for (int j = 0; j < 16; ++j)
            if (x[j] >= t2) mask |= (1u << j);
        // x[] dead from here (fallback reloads via __ldg).
    }

    const float thr1 = m1 * (m1 > 0.0f ? 0.8f : 1.25f);
    const float c1   = -m1 * L2E;

    // ---- C: sparse gather ----
    float s1 = 0.0f, s2 = 0.0f;
    int mi1 = 127, mi2 = 127;
    while (mask) {
        const int j = __ffs(mask) - 1;
        mask &= mask - 1;
        const int gj = ((j & ~3) << 2) + lane_off + (j & 3);  // expert index
        const float v = __ldg(rowp + gj);    // L1 hit (row just loaded)
        const float e = ex2(fmaf(v, L2E, c1));
        s2 += e;
        if (v >= thr1) s1 += e;
        if (v == m1) mi1 = min(mi1, gj);
        if (v == m2) mi2 = min(mi2, gj);
    }

    // ---- D: fused group reduction: sums + index mins ----
    #pragma unroll
    for (int off = 2; off > 0; off >>= 1) {
        s1 += __shfl_xor_sync(0xffffffffu, s1, off);
        s2 += __shfl_xor_sync(0xffffffffu, s2, off);
        mi1 = min(mi1, __shfl_xor_sync(0xffffffffu, mi1, off));
        mi2 = min(mi2, __shfl_xor_sync(0xffffffffu, mi2, off));
    }

    // ---- rare exact-tie fallback: m1 == m2 -> lowest m2-pos excluding mi1 ----
    if (__ballot_sync(0xffffffffu, m1 == m2)) {
        int sec = 127;
        #pragma unroll
        for (int j = 0; j < 16; ++j) {
            const int gj = ((j & ~3) << 2) + lane_off + (j & 3);
            const float v = __ldg(rowp + gj);   // L1-hot
            if (v == m2 && gj != mi1) sec = min(sec, gj);
        }
        #pragma unroll
        for (int off = 2; off > 0; off >>= 1)
            sec = min(sec, __shfl_xor_sync(0xffffffffu, sec, off));
        if (m1 == m2) mi2 = sec;
    }

    const float sel1 = rcp(s1);
    const float sel2 = ex2(fmaf(m2, L2E, c1)) * rcp(s2 - 1.0f);

    if (sub == 0 && valid) {
        reinterpret_cast<float2*>(out)[token] =
            make_float2((float)mi1, (float)mi2);
        reinterpret_cast<float2*>(out + 2 * (size_t)n_tokens)[token] =
            make_float2(sel1, sel2);
    }
}

extern "C" void kernel_launch(void* const* d_in, const int* in_sizes, int n_in,
                              void* d_out, int out_size) {
    const float* logits = (const float*)d_in[0];
    const int n_tokens  = in_sizes[0] / NUM_EXPERTS;

    float* out = (float*)d_out;

    const int threads = 128;                 // 4 warps = 32 tokens/block
    const int tokens_per_block = (threads / 32) * 8;
    const int blocks = (n_tokens + tokens_per_block - 1) / tokens_per_block;
    sparse_mixer_routing_kernel<<<blocks, threads>>>(logits, out, n_tokens);
}